// round 1
// baseline (speedup 1.0000x reference)
#include <cuda_runtime.h>
#include <math.h>

#define BB 16
#define TT 16384
#define DD 128
#define HH 256
#define NS 9            // S-partial slots per batch -> 144 CTAs (one wave on 148 SMs)
#define NTILES (TT/128) // 128 tiles per batch
#define EPSV 1e-5f

#define SXS 129         // stride for [t][d] buffers (scalar column reads conflict-free)
#define SPS 132         // stride for [t][i] buffers (float4 row ops, mult of 4)

// ---------------- device scratch (allocation-free: __device__ globals) ----------------
__device__ __align__(16) float g_M1T[DD*DD];
__device__ __align__(16) float g_M2T[DD*DD];
__device__ __align__(16) float g_N1T[DD*DD];
__device__ __align__(16) float g_N2T[DD*DD];
__device__ __align__(16) float g_WvT[DD*DD];
__device__ __align__(16) float g_WoT[DD*DD];
__device__ __align__(16) float g_phiq[(size_t)BB*TT*DD];      // 128 MB
__device__ __align__(16) float g_Spart[(size_t)BB*NS*DD*DD];  // 9.4 MB
__device__ __align__(16) float g_S[(size_t)BB*DD*DD];         // 1 MB
__device__ unsigned int g_poolbits[BB*DD];

// ---------------- P0: fold feature-map weights, transpose to k-major ----------------
__global__ void k_prep(const float* __restrict__ Wq, const float* __restrict__ Wk,
                       const float* __restrict__ Wv,
                       const float* __restrict__ fq1, const float* __restrict__ fq2,
                       const float* __restrict__ fk1, const float* __restrict__ fk2,
                       const float* __restrict__ Wo)
{
    int m = blockIdx.x;
    const float* A = nullptr; const float* Wb = nullptr; float* out = nullptr;
    switch (m) {
        case 0: A = fq1; Wb = Wq; out = g_M1T; break;
        case 1: A = fq2; Wb = Wq; out = g_M2T; break;
        case 2: A = fk1; Wb = Wk; out = g_N1T; break;
        case 3: A = fk2; Wb = Wk; out = g_N2T; break;
        case 4: out = g_WvT; break;
        case 5: out = g_WoT; break;
    }
    if (m < 4) {
        // out[d][i] = sum_l A[i][l] * Wb[l][d]   (stored k-major: row = d)
        for (int e = threadIdx.x; e < DD*DD; e += blockDim.x) {
            int d = e >> 7, i = e & 127;
            float s = 0.f;
            #pragma unroll 8
            for (int l = 0; l < DD; l++) s = fmaf(A[i*DD + l], Wb[l*DD + d], s);
            out[d*DD + i] = s;
        }
    } else {
        const float* src = (m == 4) ? Wv : Wo;
        for (int e = threadIdx.x; e < DD*DD; e += blockDim.x) {
            int d = e >> 7, i = e & 127;
            out[d*DD + i] = src[i*DD + d];   // transpose
        }
    }
}

__global__ void k_init()
{
    for (int i = threadIdx.x; i < BB*DD; i += blockDim.x) g_poolbits[i] = 0u;
}

// ---------------- shared GEMM microkernel ----------------
// C[t][i] = sum_k sA[t*SXS + k] * Wt[k*128 + i],  t,i in [0,128), k in [0,128)
// Wt streamed from global through wbuf in 32-row chunks. 256 threads, 8x8 per thread.
__device__ __forceinline__ void gemm128(const float* __restrict__ Wt,
                                        const float* __restrict__ sA,
                                        float* wbuf, float acc[64],
                                        int ty, int tx, int tid)
{
    #pragma unroll
    for (int i = 0; i < 64; i++) acc[i] = 0.f;
    for (int kc = 0; kc < 128; kc += 32) {
        __syncthreads();
        #pragma unroll
        for (int i = 0; i < 4; i++) {
            int L = i*256 + tid;          // float4 index 0..1023
            int r = L >> 5, c = (L & 31) << 2;
            float4 w = *reinterpret_cast<const float4*>(Wt + (kc + r)*128 + c);
            *reinterpret_cast<float4*>(wbuf + r*128 + c) = w;
        }
        __syncthreads();
        #pragma unroll
        for (int kk = 0; kk < 32; kk++) {
            float a[8], b[8];
            #pragma unroll
            for (int j = 0; j < 8; j++) a[j] = sA[(ty*8 + j)*SXS + kc + kk];
            float4 b0 = *reinterpret_cast<const float4*>(wbuf + kk*128 + tx*8);
            float4 b1 = *reinterpret_cast<const float4*>(wbuf + kk*128 + tx*8 + 4);
            b[0]=b0.x; b[1]=b0.y; b[2]=b0.z; b[3]=b0.w;
            b[4]=b1.x; b[5]=b1.y; b[6]=b1.z; b[7]=b1.w;
            #pragma unroll
            for (int j = 0; j < 8; j++)
                #pragma unroll
                for (int q = 0; q < 8; q++)
                    acc[j*8 + q] = fmaf(a[j], b[q], acc[j*8 + q]);
        }
    }
}

__device__ __forceinline__ void store_acc_sps(float* dst, const float acc[64], int ty, int tx)
{
    #pragma unroll
    for (int j = 0; j < 8; j++) {
        float4 a = make_float4(acc[j*8+0], acc[j*8+1], acc[j*8+2], acc[j*8+3]);
        float4 b = make_float4(acc[j*8+4], acc[j*8+5], acc[j*8+6], acc[j*8+7]);
        *reinterpret_cast<float4*>(dst + (ty*8 + j)*SPS + tx*8)     = a;
        *reinterpret_cast<float4*>(dst + (ty*8 + j)*SPS + tx*8 + 4) = b;
    }
}

// ---------------- P1: phi(q), phi(k), v, and S partial accumulation ----------------
// grid (NS, BB), 256 threads. Each CTA owns tiles {slot, slot+NS, ...} of its batch and
// keeps its S-partial in 64 registers across tiles (deterministic reduction afterwards).
__global__ void __launch_bounds__(256, 1)
k_pass1(const float* __restrict__ x,
        const float* __restrict__ bq1, const float* __restrict__ bq2,
        const float* __restrict__ bk1, const float* __restrict__ bk2)
{
    extern __shared__ float smem[];
    float* sX    = smem;                  // [128][SXS]
    float* sPhik = sX    + 128*SXS;       // [128][SPS]
    float* sV    = sPhik + 128*SPS;       // [128][SPS]
    float* wbuf  = sV    + 128*SPS;       // [32][128]
    float* sb    = wbuf  + 32*128;        // [4][128] biases

    int tid = threadIdx.x, tx = tid & 15, ty = tid >> 4;
    int slot = blockIdx.x, b = blockIdx.y;

    if (tid < 128) {
        sb[tid]       = bq1[tid];
        sb[128 + tid] = bq2[tid];
        sb[256 + tid] = bk1[tid];
        sb[384 + tid] = bk2[tid];
    }

    float Sacc[64];
    #pragma unroll
    for (int i = 0; i < 64; i++) Sacc[i] = 0.f;
    float acc[64];

    const float* xb = x + (size_t)b*TT*DD;

    for (int tile = slot; tile < NTILES; tile += NS) {
        int tt = tile*128;
        __syncthreads();   // protects sX / sPhik / sV from prior-iteration readers
        // load x tile [128 tok][128 d] -> sX (stride SXS), scalar smem writes
        #pragma unroll
        for (int i = 0; i < 16; i++) {
            int L = i*256 + tid;          // float4 idx 0..4095
            int t = L >> 5, c = (L & 31) << 2;
            float4 v4 = *reinterpret_cast<const float4*>(xb + (size_t)(tt + t)*DD + c);
            float* p = sX + t*SXS + c;
            p[0] = v4.x; p[1] = v4.y; p[2] = v4.z; p[3] = v4.w;
        }
        // (gemm128's leading __syncthreads orders sX writes before reads)

        // (1) a1 = x @ M1^T -> sV (temp)
        gemm128(g_M1T, sX, wbuf, acc, ty, tx, tid);
        store_acc_sps(sV, acc, ty, tx);
        // (2) a2 = x @ M2^T ; phiq = (a1+b1)*(a2+b2) -> global
        gemm128(g_M2T, sX, wbuf, acc, ty, tx, tid);
        {
            float* phiqb = g_phiq + ((size_t)b*TT + tt)*DD;
            #pragma unroll
            for (int j = 0; j < 8; j++) {
                int t = ty*8 + j;
                float o[8];
                #pragma unroll
                for (int q = 0; q < 8; q++) {
                    int c = tx*8 + q;
                    float v1 = sV[t*SPS + c] + sb[c];
                    float v2 = acc[j*8 + q]  + sb[128 + c];
                    o[q] = v1 * v2;
                }
                *reinterpret_cast<float4*>(phiqb + (size_t)t*DD + tx*8) =
                    make_float4(o[0], o[1], o[2], o[3]);
                *reinterpret_cast<float4*>(phiqb + (size_t)t*DD + tx*8 + 4) =
                    make_float4(o[4], o[5], o[6], o[7]);
            }
        }
        // (3) k1 = x @ N1^T -> sPhik
        gemm128(g_N1T, sX, wbuf, acc, ty, tx, tid);
        store_acc_sps(sPhik, acc, ty, tx);
        // (4) k2 = x @ N2^T ; phik = (k1+bk1)*(k2+bk2) in place (own 8x8 block)
        gemm128(g_N2T, sX, wbuf, acc, ty, tx, tid);
        #pragma unroll
        for (int j = 0; j < 8; j++) {
            int t = ty*8 + j;
            #pragma unroll
            for (int q = 0; q < 8; q++) {
                int c = tx*8 + q;
                float v1 = sPhik[t*SPS + c] + sb[256 + c];
                float v2 = acc[j*8 + q]     + sb[384 + c];
                sPhik[t*SPS + c] = v1 * v2;
            }
        }
        // (5) v = x @ Wv^T -> sV
        gemm128(g_WvT, sX, wbuf, acc, ty, tx, tid);
        store_acc_sps(sV, acc, ty, tx);
        __syncthreads();
        // (6) S += phik^T @ v   (rank-128 update into persistent registers)
        #pragma unroll 2
        for (int t = 0; t < 128; t++) {
            float4 a0 = *reinterpret_cast<const float4*>(sPhik + t*SPS + ty*8);
            float4 a1 = *reinterpret_cast<const float4*>(sPhik + t*SPS + ty*8 + 4);
            float4 v0 = *reinterpret_cast<const float4*>(sV    + t*SPS + tx*8);
            float4 v1 = *reinterpret_cast<const float4*>(sV    + t*SPS + tx*8 + 4);
            float av[8] = {a0.x,a0.y,a0.z,a0.w,a1.x,a1.y,a1.z,a1.w};
            float bv[8] = {v0.x,v0.y,v0.z,v0.w,v1.x,v1.y,v1.z,v1.w};
            #pragma unroll
            for (int j = 0; j < 8; j++)
                #pragma unroll
                for (int q = 0; q < 8; q++)
                    Sacc[j*8 + q] = fmaf(av[j], bv[q], Sacc[j*8 + q]);
        }
    }

    float* sp = g_Spart + (size_t)(b*NS + slot)*DD*DD;
    #pragma unroll
    for (int j = 0; j < 8; j++) {
        *reinterpret_cast<float4*>(sp + (ty*8 + j)*DD + tx*8) =
            make_float4(Sacc[j*8+0], Sacc[j*8+1], Sacc[j*8+2], Sacc[j*8+3]);
        *reinterpret_cast<float4*>(sp + (ty*8 + j)*DD + tx*8 + 4) =
            make_float4(Sacc[j*8+4], Sacc[j*8+5], Sacc[j*8+6], Sacc[j*8+7]);
    }
}

// ---------------- deterministic S reduction ----------------
__global__ void k_reduceS()
{
    int idx = blockIdx.x*256 + threadIdx.x;
    if (idx < BB*DD*DD) {
        int b = idx >> 14, e = idx & 16383;
        float s = 0.f;
        #pragma unroll
        for (int p = 0; p < NS; p++)
            s += g_Spart[((size_t)b*NS + p)*DD*DD + e];
        g_S[idx] = s;
    }
}

// ---------------- P2: o = phiq@S -> RMSNorm -> @Wo^T -> tile max -> atomicMax ----------------
__global__ void __launch_bounds__(256, 1)
k_pass2(const float* __restrict__ rms_w)
{
    extern __shared__ float smem[];
    float* sQ   = smem;               // [128][SXS]
    float* sO   = sQ   + 128*SXS;     // [128][SXS]
    float* wbuf = sO   + 128*SXS;     // [32][128]
    float* red  = wbuf + 32*128;      // [16][128]

    int tid = threadIdx.x, tx = tid & 15, ty = tid >> 4;
    int tile = blockIdx.x, b = blockIdx.y;
    int tt = tile*128;

    const float* qb = g_phiq + ((size_t)b*TT + tt)*DD;
    #pragma unroll
    for (int i = 0; i < 16; i++) {
        int L = i*256 + tid;
        int t = L >> 5, c = (L & 31) << 2;
        float4 v4 = *reinterpret_cast<const float4*>(qb + (size_t)t*DD + c);
        float* p = sQ + t*SXS + c;
        p[0] = v4.x; p[1] = v4.y; p[2] = v4.z; p[3] = v4.w;
    }

    float acc[64];
    // o = phiq @ S_b
    gemm128(g_S + (size_t)b*DD*DD, sQ, wbuf, acc, ty, tx, tid);
    #pragma unroll
    for (int j = 0; j < 8; j++)
        #pragma unroll
        for (int q = 0; q < 8; q++)
            sO[(ty*8 + j)*SXS + tx*8 + q] = acc[j*8 + q];
    __syncthreads();

    // RMSNorm per token row (warp per row)
    int warp = tid >> 5, lane = tid & 31;
    float rw0 = rms_w[lane], rw1 = rms_w[lane + 32],
          rw2 = rms_w[lane + 64], rw3 = rms_w[lane + 96];
    for (int r = warp; r < 128; r += 8) {
        float v0 = sO[r*SXS + lane],      v1 = sO[r*SXS + lane + 32];
        float v2 = sO[r*SXS + lane + 64], v3 = sO[r*SXS + lane + 96];
        float ss = v0*v0 + v1*v1 + v2*v2 + v3*v3;
        #pragma unroll
        for (int off = 16; off; off >>= 1) ss += __shfl_xor_sync(0xffffffffu, ss, off);
        float sc = rsqrtf(ss*(1.0f/128.0f) + EPSV);
        sO[r*SXS + lane]      = v0*sc*rw0;
        sO[r*SXS + lane + 32] = v1*sc*rw1;
        sO[r*SXS + lane + 64] = v2*sc*rw2;
        sO[r*SXS + lane + 96] = v3*sc*rw3;
    }
    __syncthreads();

    // z = o_norm @ Wo^T
    gemm128(g_WoT, sO, wbuf, acc, ty, tx, tid);

    // column max over this thread's 8 rows, then over ty, then global atomicMax
    float mx[8];
    #pragma unroll
    for (int q = 0; q < 8; q++) {
        float m = acc[q];
        #pragma unroll
        for (int j = 1; j < 8; j++) m = fmaxf(m, acc[j*8 + q]);
        mx[q] = m;
    }
    #pragma unroll
    for (int q = 0; q < 8; q++) red[ty*128 + tx*8 + q] = mx[q];
    __syncthreads();
    if (tid < 128) {
        float m = red[tid];
        #pragma unroll
        for (int i = 1; i < 16; i++) m = fmaxf(m, red[i*128 + tid]);
        unsigned int bits = __float_as_uint(m);
        bits = (bits & 0x80000000u) ? ~bits : (bits | 0x80000000u);
        atomicMax(&g_poolbits[b*DD + tid], bits);
    }
}

// ---------------- P3: out = pooled @ Wp^T + bp ----------------
__global__ void k_final(const float* __restrict__ Wp, const float* __restrict__ bp,
                        float* __restrict__ out)
{
    __shared__ float sp[DD];
    int b = blockIdx.x;
    int h = threadIdx.x;
    if (h < DD) {
        unsigned int e = g_poolbits[b*DD + h];
        e = (e & 0x80000000u) ? (e & 0x7fffffffu) : ~e;
        sp[h] = __uint_as_float(e);
    }
    __syncthreads();
    float s = bp[h];
    #pragma unroll 8
    for (int d = 0; d < DD; d++) s = fmaf(sp[d], Wp[h*DD + d], s);
    out[b*HH + h] = s;
}

// ---------------- launch ----------------
extern "C" void kernel_launch(void* const* d_in, const int* in_sizes, int n_in,
                              void* d_out, int out_size)
{
    (void)in_sizes; (void)n_in; (void)out_size;
    const float* x    = (const float*)d_in[0];
    const float* Wq   = (const float*)d_in[1];
    const float* Wk   = (const float*)d_in[2];
    const float* Wv   = (const float*)d_in[3];
    const float* fq1  = (const float*)d_in[4];
    const float* bq1  = (const float*)d_in[5];
    const float* fq2  = (const float*)d_in[6];
    const float* bq2  = (const float*)d_in[7];
    const float* fk1  = (const float*)d_in[8];
    const float* bk1  = (const float*)d_in[9];
    const float* fk2  = (const float*)d_in[10];
    const float* bk2  = (const float*)d_in[11];
    const float* rmsw = (const float*)d_in[12];
    const float* Wo   = (const float*)d_in[13];
    const float* Wp   = (const float*)d_in[14];
    const float* bp   = (const float*)d_in[15];
    float* out = (float*)d_out;

    const int SMEM1 = (128*SXS + 2*128*SPS + 32*128 + 4*128) * (int)sizeof(float); // 219648
    const int SMEM2 = (2*128*SXS + 32*128 + 16*128) * (int)sizeof(float);          // 156672
    cudaFuncSetAttribute(k_pass1, cudaFuncAttributeMaxDynamicSharedMemorySize, SMEM1);
    cudaFuncSetAttribute(k_pass2, cudaFuncAttributeMaxDynamicSharedMemorySize, SMEM2);

    k_prep<<<6, 256>>>(Wq, Wk, Wv, fq1, fq2, fk1, fk2, Wo);
    k_init<<<1, 256>>>();
    k_pass1<<<dim3(NS, BB), 256, SMEM1>>>(x, bq1, bq2, bk1, bk2);
    k_reduceS<<<(BB*DD*DD + 255)/256, 256>>>();
    k_pass2<<<dim3(NTILES, BB), 256, SMEM2>>>(rmsw);
    k_final<<<BB, HH>>>(Wp, bp, out);
}

// round 5
// speedup vs baseline: 1.0040x; 1.0040x over previous
#include <cuda_runtime.h>
#include <math.h>

#define BB 16
#define TT 16384
#define DD 128
#define HH 256
#define NS 9            // S-partial slots per batch -> 144 CTAs (one wave on 148 SMs)
#define NTILES (TT/128) // 128 tiles per batch
#define EPSV 1e-5f

#define SXS 129         // stride for [t][d] buffers (scalar column reads conflict-free)
#define SPS 132         // stride for [t][i] buffers (float4 row ops, mult of 4)

// ---------------- device scratch (allocation-free: __device__ globals) ----------------
__device__ __align__(16) float g_M1T[DD*DD];
__device__ __align__(16) float g_M2T[DD*DD];
__device__ __align__(16) float g_N1T[DD*DD];
__device__ __align__(16) float g_N2T[DD*DD];
__device__ __align__(16) float g_WvT[DD*DD];
__device__ __align__(16) float g_WoT[DD*DD];
__device__ __align__(16) float g_phiq[(size_t)BB*TT*DD];      // 128 MB
__device__ __align__(16) float g_Spart[(size_t)BB*NS*DD*DD];  // 9.4 MB
__device__ __align__(16) float g_S[(size_t)BB*DD*DD];         // 1 MB
__device__ unsigned int g_poolbits[BB*DD];

// ---------------- P0: fold feature-map weights, transpose to k-major ----------------
__global__ void k_prep(const float* __restrict__ Wq, const float* __restrict__ Wk,
                       const float* __restrict__ Wv,
                       const float* __restrict__ fq1, const float* __restrict__ fq2,
                       const float* __restrict__ fk1, const float* __restrict__ fk2,
                       const float* __restrict__ Wo)
{
    int m = blockIdx.x;
    const float* A = nullptr; const float* Wb = nullptr; float* out = nullptr;
    switch (m) {
        case 0: A = fq1; Wb = Wq; out = g_M1T; break;
        case 1: A = fq2; Wb = Wq; out = g_M2T; break;
        case 2: A = fk1; Wb = Wk; out = g_N1T; break;
        case 3: A = fk2; Wb = Wk; out = g_N2T; break;
        case 4: out = g_WvT; break;
        case 5: out = g_WoT; break;
    }
    if (m < 4) {
        // out[d][i] = sum_l A[i][l] * Wb[l][d]   (stored k-major: row = d)
        for (int e = threadIdx.x; e < DD*DD; e += blockDim.x) {
            int d = e >> 7, i = e & 127;
            float s = 0.f;
            #pragma unroll 8
            for (int l = 0; l < DD; l++) s = fmaf(A[i*DD + l], Wb[l*DD + d], s);
            out[d*DD + i] = s;
        }
    } else {
        const float* src = (m == 4) ? Wv : Wo;
        for (int e = threadIdx.x; e < DD*DD; e += blockDim.x) {
            int d = e >> 7, i = e & 127;
            out[d*DD + i] = src[i*DD + d];   // transpose
        }
    }
}

__global__ void k_init()
{
    for (int i = threadIdx.x; i < BB*DD; i += blockDim.x) g_poolbits[i] = 0u;
}

// ---------------- shared GEMM microkernel ----------------
// C[t][i] = sum_k sA[t*SXS + k] * Wt[k*128 + i],  t,i in [0,128), k in [0,128)
// Wt streamed from global through wbuf in 32-row chunks. 256 threads, 8x8 per thread.
__device__ __forceinline__ void gemm128(const float* __restrict__ Wt,
                                        const float* __restrict__ sA,
                                        float* wbuf, float acc[64],
                                        int ty, int tx, int tid)
{
    #pragma unroll
    for (int i = 0; i < 64; i++) acc[i] = 0.f;
    for (int kc = 0; kc < 128; kc += 32) {
        __syncthreads();
        #pragma unroll
        for (int i = 0; i < 4; i++) {
            int L = i*256 + tid;          // float4 index 0..1023
            int r = L >> 5, c = (L & 31) << 2;
            float4 w = *reinterpret_cast<const float4*>(Wt + (kc + r)*128 + c);
            *reinterpret_cast<float4*>(wbuf + r*128 + c) = w;
        }
        __syncthreads();
        #pragma unroll
        for (int kk = 0; kk < 32; kk++) {
            float a[8], b[8];
            #pragma unroll
            for (int j = 0; j < 8; j++) a[j] = sA[(ty*8 + j)*SXS + kc + kk];
            float4 b0 = *reinterpret_cast<const float4*>(wbuf + kk*128 + tx*8);
            float4 b1 = *reinterpret_cast<const float4*>(wbuf + kk*128 + tx*8 + 4);
            b[0]=b0.x; b[1]=b0.y; b[2]=b0.z; b[3]=b0.w;
            b[4]=b1.x; b[5]=b1.y; b[6]=b1.z; b[7]=b1.w;
            #pragma unroll
            for (int j = 0; j < 8; j++)
                #pragma unroll
                for (int q = 0; q < 8; q++)
                    acc[j*8 + q] = fmaf(a[j], b[q], acc[j*8 + q]);
        }
    }
}

__device__ __forceinline__ void store_acc_sps(float* dst, const float acc[64], int ty, int tx)
{
    #pragma unroll
    for (int j = 0; j < 8; j++) {
        float4 a = make_float4(acc[j*8+0], acc[j*8+1], acc[j*8+2], acc[j*8+3]);
        float4 b = make_float4(acc[j*8+4], acc[j*8+5], acc[j*8+6], acc[j*8+7]);
        *reinterpret_cast<float4*>(dst + (ty*8 + j)*SPS + tx*8)     = a;
        *reinterpret_cast<float4*>(dst + (ty*8 + j)*SPS + tx*8 + 4) = b;
    }
}

// ---------------- P1: phi(q), phi(k), v, and S partial accumulation ----------------
// grid (NS, BB), 256 threads. Each CTA owns tiles {slot, slot+NS, ...} of its batch and
// keeps its S-partial in 64 registers across tiles (deterministic reduction afterwards).
__global__ void __launch_bounds__(256, 1)
k_pass1(const float* __restrict__ x,
        const float* __restrict__ bq1, const float* __restrict__ bq2,
        const float* __restrict__ bk1, const float* __restrict__ bk2)
{
    extern __shared__ float smem[];
    float* sX    = smem;                  // [128][SXS]
    float* sPhik = sX    + 128*SXS;       // [128][SPS]
    float* sV    = sPhik + 128*SPS;       // [128][SPS]
    float* wbuf  = sV    + 128*SPS;       // [32][128]
    float* sb    = wbuf  + 32*128;        // [4][128] biases

    int tid = threadIdx.x, tx = tid & 15, ty = tid >> 4;
    int slot = blockIdx.x, b = blockIdx.y;

    if (tid < 128) {
        sb[tid]       = bq1[tid];
        sb[128 + tid] = bq2[tid];
        sb[256 + tid] = bk1[tid];
        sb[384 + tid] = bk2[tid];
    }

    float Sacc[64];
    #pragma unroll
    for (int i = 0; i < 64; i++) Sacc[i] = 0.f;
    float acc[64];

    const float* xb = x + (size_t)b*TT*DD;

    for (int tile = slot; tile < NTILES; tile += NS) {
        int tt = tile*128;
        __syncthreads();   // protects sX / sPhik / sV from prior-iteration readers
        // load x tile [128 tok][128 d] -> sX (stride SXS), scalar smem writes
        #pragma unroll
        for (int i = 0; i < 16; i++) {
            int L = i*256 + tid;          // float4 idx 0..4095
            int t = L >> 5, c = (L & 31) << 2;
            float4 v4 = *reinterpret_cast<const float4*>(xb + (size_t)(tt + t)*DD + c);
            float* p = sX + t*SXS + c;
            p[0] = v4.x; p[1] = v4.y; p[2] = v4.z; p[3] = v4.w;
        }
        // (gemm128's leading __syncthreads orders sX writes before reads)

        // (1) a1 = x @ M1^T -> sV (temp)
        gemm128(g_M1T, sX, wbuf, acc, ty, tx, tid);
        store_acc_sps(sV, acc, ty, tx);
        // (2) a2 = x @ M2^T ; phiq = (a1+b1)*(a2+b2) -> global
        gemm128(g_M2T, sX, wbuf, acc, ty, tx, tid);
        {
            float* phiqb = g_phiq + ((size_t)b*TT + tt)*DD;
            #pragma unroll
            for (int j = 0; j < 8; j++) {
                int t = ty*8 + j;
                float o[8];
                #pragma unroll
                for (int q = 0; q < 8; q++) {
                    int c = tx*8 + q;
                    float v1 = sV[t*SPS + c] + sb[c];
                    float v2 = acc[j*8 + q]  + sb[128 + c];
                    o[q] = v1 * v2;
                }
                *reinterpret_cast<float4*>(phiqb + (size_t)t*DD + tx*8) =
                    make_float4(o[0], o[1], o[2], o[3]);
                *reinterpret_cast<float4*>(phiqb + (size_t)t*DD + tx*8 + 4) =
                    make_float4(o[4], o[5], o[6], o[7]);
            }
        }
        // (3) k1 = x @ N1^T -> sPhik
        gemm128(g_N1T, sX, wbuf, acc, ty, tx, tid);
        store_acc_sps(sPhik, acc, ty, tx);
        // (4) k2 = x @ N2^T ; phik = (k1+bk1)*(k2+bk2) in place (own 8x8 block)
        gemm128(g_N2T, sX, wbuf, acc, ty, tx, tid);
        #pragma unroll
        for (int j = 0; j < 8; j++) {
            int t = ty*8 + j;
            #pragma unroll
            for (int q = 0; q < 8; q++) {
                int c = tx*8 + q;
                float v1 = sPhik[t*SPS + c] + sb[256 + c];
                float v2 = acc[j*8 + q]     + sb[384 + c];
                sPhik[t*SPS + c] = v1 * v2;
            }
        }
        // (5) v = x @ Wv^T -> sV
        gemm128(g_WvT, sX, wbuf, acc, ty, tx, tid);
        store_acc_sps(sV, acc, ty, tx);
        __syncthreads();
        // (6) S += phik^T @ v   (rank-128 update into persistent registers)
        #pragma unroll 2
        for (int t = 0; t < 128; t++) {
            float4 a0 = *reinterpret_cast<const float4*>(sPhik + t*SPS + ty*8);
            float4 a1 = *reinterpret_cast<const float4*>(sPhik + t*SPS + ty*8 + 4);
            float4 v0 = *reinterpret_cast<const float4*>(sV    + t*SPS + tx*8);
            float4 v1 = *reinterpret_cast<const float4*>(sV    + t*SPS + tx*8 + 4);
            float av[8] = {a0.x,a0.y,a0.z,a0.w,a1.x,a1.y,a1.z,a1.w};
            float bv[8] = {v0.x,v0.y,v0.z,v0.w,v1.x,v1.y,v1.z,v1.w};
            #pragma unroll
            for (int j = 0; j < 8; j++)
                #pragma unroll
                for (int q = 0; q < 8; q++)
                    Sacc[j*8 + q] = fmaf(av[j], bv[q], Sacc[j*8 + q]);
        }
    }

    float* sp = g_Spart + (size_t)(b*NS + slot)*DD*DD;
    #pragma unroll
    for (int j = 0; j < 8; j++) {
        *reinterpret_cast<float4*>(sp + (ty*8 + j)*DD + tx*8) =
            make_float4(Sacc[j*8+0], Sacc[j*8+1], Sacc[j*8+2], Sacc[j*8+3]);
        *reinterpret_cast<float4*>(sp + (ty*8 + j)*DD + tx*8 + 4) =
            make_float4(Sacc[j*8+4], Sacc[j*8+5], Sacc[j*8+6], Sacc[j*8+7]);
    }
}

// ---------------- deterministic S reduction ----------------
__global__ void k_reduceS()
{
    int idx = blockIdx.x*256 + threadIdx.x;
    if (idx < BB*DD*DD) {
        int b = idx >> 14, e = idx & 16383;
        float s = 0.f;
        #pragma unroll
        for (int p = 0; p < NS; p++)
            s += g_Spart[((size_t)b*NS + p)*DD*DD + e];
        g_S[idx] = s;
    }
}

// ---------------- P2: o = phiq@S -> RMSNorm -> @Wo^T -> tile max -> atomicMax ----------------
__global__ void __launch_bounds__(256, 1)
k_pass2(const float* __restrict__ rms_w)
{
    extern __shared__ float smem[];
    float* sQ   = smem;               // [128][SXS]
    float* sO   = sQ   + 128*SXS;     // [128][SXS]
    float* wbuf = sO   + 128*SXS;     // [32][128]
    float* red  = wbuf + 32*128;      // [16][128]

    int tid = threadIdx.x, tx = tid & 15, ty = tid >> 4;
    int tile = blockIdx.x, b = blockIdx.y;
    int tt = tile*128;

    const float* qb = g_phiq + ((size_t)b*TT + tt)*DD;
    #pragma unroll
    for (int i = 0; i < 16; i++) {
        int L = i*256 + tid;
        int t = L >> 5, c = (L & 31) << 2;
        float4 v4 = *reinterpret_cast<const float4*>(qb + (size_t)t*DD + c);
        float* p = sQ + t*SXS + c;
        p[0] = v4.x; p[1] = v4.y; p[2] = v4.z; p[3] = v4.w;
    }

    float acc[64];
    // o = phiq @ S_b
    gemm128(g_S + (size_t)b*DD*DD, sQ, wbuf, acc, ty, tx, tid);
    #pragma unroll
    for (int j = 0; j < 8; j++)
        #pragma unroll
        for (int q = 0; q < 8; q++)
            sO[(ty*8 + j)*SXS + tx*8 + q] = acc[j*8 + q];
    __syncthreads();

    // RMSNorm per token row (warp per row)
    int warp = tid >> 5, lane = tid & 31;
    float rw0 = rms_w[lane], rw1 = rms_w[lane + 32],
          rw2 = rms_w[lane + 64], rw3 = rms_w[lane + 96];
    for (int r = warp; r < 128; r += 8) {
        float v0 = sO[r*SXS + lane],      v1 = sO[r*SXS + lane + 32];
        float v2 = sO[r*SXS + lane + 64], v3 = sO[r*SXS + lane + 96];
        float ss = v0*v0 + v1*v1 + v2*v2 + v3*v3;
        #pragma unroll
        for (int off = 16; off; off >>= 1) ss += __shfl_xor_sync(0xffffffffu, ss, off);
        float sc = rsqrtf(ss*(1.0f/128.0f) + EPSV);
        sO[r*SXS + lane]      = v0*sc*rw0;
        sO[r*SXS + lane + 32] = v1*sc*rw1;
        sO[r*SXS + lane + 64] = v2*sc*rw2;
        sO[r*SXS + lane + 96] = v3*sc*rw3;
    }
    __syncthreads();

    // z = o_norm @ Wo^T
    gemm128(g_WoT, sO, wbuf, acc, ty, tx, tid);

    // column max over this thread's 8 rows, then over ty, then global atomicMax
    float mx[8];
    #pragma unroll
    for (int q = 0; q < 8; q++) {
        float m = acc[q];
        #pragma unroll
        for (int j = 1; j < 8; j++) m = fmaxf(m, acc[j*8 + q]);
        mx[q] = m;
    }
    #pragma unroll
    for (int q = 0; q < 8; q++) red[ty*128 + tx*8 + q] = mx[q];
    __syncthreads();
    if (tid < 128) {
        float m = red[tid];
        #pragma unroll
        for (int i = 1; i < 16; i++) m = fmaxf(m, red[i*128 + tid]);
        unsigned int bits = __float_as_uint(m);
        bits = (bits & 0x80000000u) ? ~bits : (bits | 0x80000000u);
        atomicMax(&g_poolbits[b*DD + tid], bits);
    }
}

// ---------------- P3: out = pooled @ Wp^T + bp ----------------
__global__ void k_final(const float* __restrict__ Wp, const float* __restrict__ bp,
                        float* __restrict__ out)
{
    __shared__ float sp[DD];
    int b = blockIdx.x;
    int h = threadIdx.x;
    if (h < DD) {
        unsigned int e = g_poolbits[b*DD + h];
        e = (e & 0x80000000u) ? (e & 0x7fffffffu) : ~e;
        sp[h] = __uint_as_float(e);
    }
    __syncthreads();
    float s = bp[h];
    #pragma unroll 8
    for (int d = 0; d < DD; d++) s = fmaf(sp[d], Wp[h*DD + d], s);
    out[b*HH + h] = s;
}

// ---------------- launch ----------------
extern "C" void kernel_launch(void* const* d_in, const int* in_sizes, int n_in,
                              void* d_out, int out_size)
{
    (void)in_sizes; (void)n_in; (void)out_size;
    const float* x    = (const float*)d_in[0];
    const float* Wq   = (const float*)d_in[1];
    const float* Wk   = (const float*)d_in[2];
    const float* Wv   = (const float*)d_in[3];
    const float* fq1  = (const float*)d_in[4];
    const float* bq1  = (const float*)d_in[5];
    const float* fq2  = (const float*)d_in[6];
    const float* bq2  = (const float*)d_in[7];
    const float* fk1  = (const float*)d_in[8];
    const float* bk1  = (const float*)d_in[9];
    const float* fk2  = (const float*)d_in[10];
    const float* bk2  = (const float*)d_in[11];
    const float* rmsw = (const float*)d_in[12];
    const float* Wo   = (const float*)d_in[13];
    const float* Wp   = (const float*)d_in[14];
    const float* bp   = (const float*)d_in[15];
    float* out = (float*)d_out;

    const int SMEM1 = (128*SXS + 2*128*SPS + 32*128 + 4*128) * (int)sizeof(float); // 219648
    const int SMEM2 = (2*128*SXS + 32*128 + 16*128) * (int)sizeof(float);          // 156672
    cudaFuncSetAttribute(k_pass1, cudaFuncAttributeMaxDynamicSharedMemorySize, SMEM1);
    cudaFuncSetAttribute(k_pass2, cudaFuncAttributeMaxDynamicSharedMemorySize, SMEM2);

    k_prep<<<6, 256>>>(Wq, Wk, Wv, fq1, fq2, fk1, fk2, Wo);
    k_init<<<1, 256>>>();
    k_pass1<<<dim3(NS, BB), 256, SMEM1>>>(x, bq1, bq2, bk1, bk2);
    k_reduceS<<<(BB*DD*DD + 255)/256, 256>>>();
    k_pass2<<<dim3(NTILES, BB), 256, SMEM2>>>(rmsw);
    k_final<<<BB, HH>>>(Wp, bp, out);
}

// round 7
// speedup vs baseline: 3.3141x; 3.3010x over previous
#include <cuda_runtime.h>
#include <cuda_bf16.h>
#include <math.h>
#include <stdint.h>

#define BB 16
#define TT 16384
#define DD 128
#define HH 256
#define NS 9
#define EPSV 1e-5f

// SMEM u32 offsets (pair-packed bf16 buffers, row stride PW u32 = 2*PW bf16)
#define PW 68
#define XH 0
#define XL 8704
#define WHo 17408
#define WLo 26112
#define THo 34816
#define TLo 43520
#define SB  52224          // float index
#define RED (SB+512)       // float index
#define SMEMB ((RED+256)*4)

// ---------------- device scratch ----------------
__device__ __align__(16) uint32_t g_WH[6*8192];
__device__ __align__(16) uint32_t g_WL[6*8192];
__device__ __align__(16) uint32_t g_SH[BB*8192];
__device__ __align__(16) uint32_t g_SL[BB*8192];
__device__ __align__(16) float    g_Spart[(size_t)BB*NS*16384];
__device__ __align__(16) uint32_t g_phiqH[(size_t)BB*TT*64];
__device__ __align__(16) uint32_t g_phiqL[(size_t)BB*TT*64];
__device__ unsigned int g_poolbits[BB*DD];

// ---------------- helpers ----------------
__device__ __forceinline__ uint32_t packbf(float x, float y){
    __nv_bfloat162 t = __floats2bfloat162_rn(x, y);
    return *reinterpret_cast<uint32_t*>(&t);
}
__device__ __forceinline__ float bflo(float x){
    __nv_bfloat16 h = __float2bfloat16_rn(x);
    return x - __bfloat162float(h);
}
__device__ __forceinline__ void split16(float x, uint16_t& h, uint16_t& l){
    __nv_bfloat16 hb = __float2bfloat16_rn(x);
    float r = x - __bfloat162float(hb);
    __nv_bfloat16 lb = __float2bfloat16_rn(r);
    h = *reinterpret_cast<uint16_t*>(&hb);
    l = *reinterpret_cast<uint16_t*>(&lb);
}
__device__ __forceinline__ void mma_bf16(float* c, const uint32_t* a, const uint32_t* b){
    asm volatile("mma.sync.aligned.m16n8k16.row.col.f32.bf16.bf16.f32 "
        "{%0,%1,%2,%3}, {%4,%5,%6,%7}, {%8,%9}, {%0,%1,%2,%3};\n"
        : "+f"(c[0]), "+f"(c[1]), "+f"(c[2]), "+f"(c[3])
        : "r"(a[0]), "r"(a[1]), "r"(a[2]), "r"(a[3]), "r"(b[0]), "r"(b[1]));
}
__device__ __forceinline__ void ldA(const uint32_t* A, int r0, int p0, uint32_t* a){
    a[0] = A[r0*PW + p0];
    a[1] = A[(r0+8)*PW + p0];
    a[2] = A[r0*PW + p0 + 4];
    a[3] = A[(r0+8)*PW + p0 + 4];
}
__device__ __forceinline__ void ldB(const uint32_t* B, int n, int p0, uint32_t* b){
    b[0] = B[n*PW + p0];
    b[1] = B[n*PW + p0 + 4];
}
// C[128x128] += A[128x128] @ B^T, A rows=m k-major, B rows=n k-major, 3-term bf16 split
template<bool ZERO>
__device__ __forceinline__ void wgemm(const uint32_t* su, int AHo, int ALo, int BHo, int BLo,
                                      float* acc, int wm, int wn, int lane)
{
    if (ZERO){
        #pragma unroll
        for (int i = 0; i < 64; i++) acc[i] = 0.f;
    }
    #pragma unroll
    for (int ks = 0; ks < 8; ks++){
        int p0 = ks*8 + (lane & 3);
        uint32_t bh[4][2], bl[4][2];
        #pragma unroll
        for (int nt = 0; nt < 4; nt++){
            int n = wn*32 + nt*8 + (lane >> 2);
            ldB(su + BHo, n, p0, bh[nt]);
            ldB(su + BLo, n, p0, bl[nt]);
        }
        #pragma unroll
        for (int mt = 0; mt < 4; mt++){
            int r0 = wm*64 + mt*16 + (lane >> 2);
            uint32_t ah[4], al[4];
            ldA(su + AHo, r0, p0, ah);
            ldA(su + ALo, r0, p0, al);
            #pragma unroll
            for (int nt = 0; nt < 4; nt++){
                float* c = acc + (mt*4 + nt)*4;
                mma_bf16(c, ah, bh[nt]);
                mma_bf16(c, ah, bl[nt]);
                mma_bf16(c, al, bh[nt]);
            }
        }
    }
}
__device__ __forceinline__ void stageW(uint32_t* su, int m, int tid){
    const uint32_t* gh = g_WH + m*8192;
    const uint32_t* gl = g_WL + m*8192;
    #pragma unroll
    for (int i = 0; i < 32; i++){
        int idx = i*256 + tid;
        int r = idx >> 6, p = idx & 63;
        su[WHo + r*PW + p] = gh[idx];
        su[WLo + r*PW + p] = gl[idx];
    }
}

// ---------------- k_prep: fold weights, split bf16 hi/lo, pair-packed ----------------
__global__ void k_prep(const float* __restrict__ Wq, const float* __restrict__ Wk,
                       const float* __restrict__ Wv,
                       const float* __restrict__ fq1, const float* __restrict__ fq2,
                       const float* __restrict__ fk1, const float* __restrict__ fk2,
                       const float* __restrict__ Wo)
{
    int m = blockIdx.x;
    const float* A = nullptr; const float* Wb = nullptr;
    switch(m){ case 0: A=fq1; Wb=Wq; break; case 1: A=fq2; Wb=Wq; break;
               case 2: A=fk1; Wb=Wk; break; case 3: A=fk2; Wb=Wk; break; }
    for (int e = threadIdx.x; e < 8192; e += blockDim.x){
        int i = e >> 6, p = e & 63;
        float s0, s1;
        if (m < 4){
            s0 = 0.f; s1 = 0.f;
            #pragma unroll 4
            for (int d = 0; d < DD; d++){
                float a = A[i*DD + d];
                s0 = fmaf(a, Wb[d*DD + 2*p],     s0);
                s1 = fmaf(a, Wb[d*DD + 2*p + 1], s1);
            }
        } else {
            const float* src = (m == 4) ? Wv : Wo;
            s0 = src[i*DD + 2*p]; s1 = src[i*DD + 2*p + 1];
        }
        g_WH[m*8192 + e] = packbf(s0, s1);
        g_WL[m*8192 + e] = packbf(bflo(s0), bflo(s1));
    }
}

__global__ void k_init(){ for (int i = threadIdx.x; i < BB*DD; i += blockDim.x) g_poolbits[i] = 0u; }

// ---------------- pass1 ----------------
__global__ void __launch_bounds__(256, 1)
k_pass1(const float* __restrict__ x,
        const float* __restrict__ bq1, const float* __restrict__ bq2,
        const float* __restrict__ bk1, const float* __restrict__ bk2)
{
    extern __shared__ uint32_t su[];
    float* sf = (float*)su;
    float* sTf = (float*)(su + THo);
    int tid = threadIdx.x, lane = tid & 31, wid = tid >> 5;
    int wm = wid & 1, wn = wid >> 1;
    int rg = lane >> 2, tg = lane & 3;
    int slot = blockIdx.x, b = blockIdx.y;

    if (tid < 128){
        sf[SB + tid]       = bq1[tid];
        sf[SB + 128 + tid] = bq2[tid];
        sf[SB + 256 + tid] = bk1[tid];
        sf[SB + 384 + tid] = bk2[tid];
    }

    float accS[64];
    #pragma unroll
    for (int i = 0; i < 64; i++) accS[i] = 0.f;
    float acc[64];

    const float* xb = x + (size_t)b*TT*DD;

    for (int tile = slot; tile < 128; tile += NS){
        int tt = tile*128;
        const float* xt = xb + (size_t)tt*DD;
        __syncthreads();
        // stage x -> XH/XL
        #pragma unroll
        for (int i = 0; i < 32; i++){
            int idx = i*256 + tid;
            int t = idx >> 6, p = idx & 63;
            float2 v = *(const float2*)(xt + t*DD + 2*p);
            su[XH + t*PW + p] = packbf(v.x, v.y);
            su[XL + t*PW + p] = packbf(bflo(v.x), bflo(v.y));
        }
        stageW(su, 0, tid);
        __syncthreads();
        // a1 = x @ M1^T
        wgemm<true>(su, XH, XL, WHo, WLo, acc, wm, wn, lane);
        #pragma unroll
        for (int mt = 0; mt < 4; mt++){
            int r0 = wm*64 + mt*16 + rg;
            #pragma unroll
            for (int nt = 0; nt < 4; nt++){
                int c0 = wn*32 + nt*8 + 2*tg, bs = (mt*4 + nt)*4;
                sTf[r0*132 + c0]       = acc[bs];
                sTf[r0*132 + c0 + 1]   = acc[bs+1];
                sTf[(r0+8)*132 + c0]   = acc[bs+2];
                sTf[(r0+8)*132 + c0+1] = acc[bs+3];
            }
        }
        __syncthreads();
        stageW(su, 1, tid);
        __syncthreads();
        // a2 = x @ M2^T ; phiq epilogue (own-thread frag locations in sTf)
        wgemm<true>(su, XH, XL, WHo, WLo, acc, wm, wn, lane);
        {
            uint32_t* gph = g_phiqH + ((size_t)(b*TT + tt))*64;
            uint32_t* gpl = g_phiqL + ((size_t)(b*TT + tt))*64;
            #pragma unroll
            for (int mt = 0; mt < 4; mt++){
                int r0 = wm*64 + mt*16 + rg, r1 = r0 + 8;
                #pragma unroll
                for (int nt = 0; nt < 4; nt++){
                    int c0 = wn*32 + nt*8 + 2*tg, bs = (mt*4 + nt)*4;
                    float u0 = (sTf[r0*132+c0]   + sf[SB+c0])  *(acc[bs]  + sf[SB+128+c0]);
                    float u1 = (sTf[r0*132+c0+1] + sf[SB+c0+1])*(acc[bs+1]+ sf[SB+128+c0+1]);
                    float u2 = (sTf[r1*132+c0]   + sf[SB+c0])  *(acc[bs+2]+ sf[SB+128+c0]);
                    float u3 = (sTf[r1*132+c0+1] + sf[SB+c0+1])*(acc[bs+3]+ sf[SB+128+c0+1]);
                    gph[r0*64 + (c0>>1)] = packbf(u0, u1);
                    gpl[r0*64 + (c0>>1)] = packbf(bflo(u0), bflo(u1));
                    gph[r1*64 + (c0>>1)] = packbf(u2, u3);
                    gpl[r1*64 + (c0>>1)] = packbf(bflo(u2), bflo(u3));
                }
            }
        }
        __syncthreads();
        stageW(su, 2, tid);
        __syncthreads();
        // k1 = x @ N1^T -> sTf
        wgemm<true>(su, XH, XL, WHo, WLo, acc, wm, wn, lane);
        #pragma unroll
        for (int mt = 0; mt < 4; mt++){
            int r0 = wm*64 + mt*16 + rg;
            #pragma unroll
            for (int nt = 0; nt < 4; nt++){
                int c0 = wn*32 + nt*8 + 2*tg, bs = (mt*4 + nt)*4;
                sTf[r0*132 + c0]       = acc[bs];
                sTf[r0*132 + c0 + 1]   = acc[bs+1];
                sTf[(r0+8)*132 + c0]   = acc[bs+2];
                sTf[(r0+8)*132 + c0+1] = acc[bs+3];
            }
        }
        __syncthreads();
        stageW(su, 3, tid);
        __syncthreads();
        // k2 = x @ N2^T ; combine phik into acc
        wgemm<true>(su, XH, XL, WHo, WLo, acc, wm, wn, lane);
        #pragma unroll
        for (int mt = 0; mt < 4; mt++){
            int r0 = wm*64 + mt*16 + rg, r1 = r0 + 8;
            #pragma unroll
            for (int nt = 0; nt < 4; nt++){
                int c0 = wn*32 + nt*8 + 2*tg, bs = (mt*4 + nt)*4;
                acc[bs]   = (sTf[r0*132+c0]   + sf[SB+256+c0])  *(acc[bs]  + sf[SB+384+c0]);
                acc[bs+1] = (sTf[r0*132+c0+1] + sf[SB+256+c0+1])*(acc[bs+1]+ sf[SB+384+c0+1]);
                acc[bs+2] = (sTf[r1*132+c0]   + sf[SB+256+c0])  *(acc[bs+2]+ sf[SB+384+c0]);
                acc[bs+3] = (sTf[r1*132+c0+1] + sf[SB+256+c0+1])*(acc[bs+3]+ sf[SB+384+c0+1]);
            }
        }
        __syncthreads();   // all sTf fp32 reads done before transposed overwrite
        // write phikT (bf16 hi/lo) into TH/TL, [d][t] halfword layout; stage Wv
        {
            uint16_t* th = (uint16_t*)(su + THo);
            uint16_t* tl = (uint16_t*)(su + TLo);
            #pragma unroll
            for (int mt = 0; mt < 4; mt++){
                int r0 = wm*64 + mt*16 + rg, r1 = r0 + 8;
                #pragma unroll
                for (int nt = 0; nt < 4; nt++){
                    int c0 = wn*32 + nt*8 + 2*tg, bs = (mt*4 + nt)*4;
                    uint16_t h, l;
                    split16(acc[bs],   h, l); th[c0*136 + r0] = h;     tl[c0*136 + r0] = l;
                    split16(acc[bs+1], h, l); th[(c0+1)*136 + r0] = h; tl[(c0+1)*136 + r0] = l;
                    split16(acc[bs+2], h, l); th[c0*136 + r1] = h;     tl[c0*136 + r1] = l;
                    split16(acc[bs+3], h, l); th[(c0+1)*136 + r1] = h; tl[(c0+1)*136 + r1] = l;
                }
            }
        }
        stageW(su, 4, tid);
        __syncthreads();
        // v = x @ Wv^T
        wgemm<true>(su, XH, XL, WHo, WLo, acc, wm, wn, lane);
        __syncthreads();   // done reading Wv
        // write vT (bf16 hi/lo) into WH/WL, [e][t] layout
        {
            uint16_t* th = (uint16_t*)(su + WHo);
            uint16_t* tl = (uint16_t*)(su + WLo);
            #pragma unroll
            for (int mt = 0; mt < 4; mt++){
                int r0 = wm*64 + mt*16 + rg, r1 = r0 + 8;
                #pragma unroll
                for (int nt = 0; nt < 4; nt++){
                    int c0 = wn*32 + nt*8 + 2*tg, bs = (mt*4 + nt)*4;
                    uint16_t h, l;
                    split16(acc[bs],   h, l); th[c0*136 + r0] = h;     tl[c0*136 + r0] = l;
                    split16(acc[bs+1], h, l); th[(c0+1)*136 + r0] = h; tl[(c0+1)*136 + r0] = l;
                    split16(acc[bs+2], h, l); th[c0*136 + r1] = h;     tl[c0*136 + r1] = l;
                    split16(acc[bs+3], h, l); th[(c0+1)*136 + r1] = h; tl[(c0+1)*136 + r1] = l;
                }
            }
        }
        __syncthreads();
        // S[d][e] += phikT @ vT^T  (A=TH/TL rows d, B=WH/WL rows e, k=t)
        wgemm<false>(su, THo, TLo, WHo, WLo, accS, wm, wn, lane);
    }
    // dump S partial [d][e]
    float* sp = g_Spart + ((size_t)(b*NS + slot) << 14);
    #pragma unroll
    for (int mt = 0; mt < 4; mt++){
        int r0 = wm*64 + mt*16 + rg, r1 = r0 + 8;
        #pragma unroll
        for (int nt = 0; nt < 4; nt++){
            int c0 = wn*32 + nt*8 + 2*tg, bs = (mt*4 + nt)*4;
            *(float2*)(sp + r0*128 + c0) = make_float2(accS[bs],   accS[bs+1]);
            *(float2*)(sp + r1*128 + c0) = make_float2(accS[bs+2], accS[bs+3]);
        }
    }
}

// ---------------- reduce S -> transposed bf16 hi/lo images [e][d-pairs] ----------------
__global__ void k_reduceS(){
    int idx = blockIdx.x*256 + threadIdx.x;
    if (idx < BB*8192){
        int b = idx >> 13, r = idx & 8191, e = r >> 6, p = r & 63;
        float s0 = 0.f, s1 = 0.f;
        #pragma unroll
        for (int ps = 0; ps < NS; ps++){
            const float* sp = g_Spart + ((size_t)(b*NS + ps) << 14);
            s0 += sp[(2*p)*128 + e];
            s1 += sp[(2*p + 1)*128 + e];
        }
        g_SH[b*8192 + e*64 + p] = packbf(s0, s1);
        g_SL[b*8192 + e*64 + p] = packbf(bflo(s0), bflo(s1));
    }
}

// ---------------- pass2 ----------------
__global__ void __launch_bounds__(256, 1)
k_pass2(const float* __restrict__ rms_w)
{
    extern __shared__ uint32_t su[];
    float* sf = (float*)su;
    float* sTf = (float*)(su + THo);
    int tid = threadIdx.x, lane = tid & 31, wid = tid >> 5;
    int wm = wid & 1, wn = wid >> 1;
    int rg = lane >> 2, tg = lane & 3;
    int tile = blockIdx.x, b = blockIdx.y, tt = tile*128;

    if (tid < 128) sf[SB + tid] = rms_w[tid];

    // stage phiq -> XH/XL, S^T -> WH/WL
    {
        const uint32_t* gh = g_phiqH + ((size_t)(b*TT + tt))*64;
        const uint32_t* gl = g_phiqL + ((size_t)(b*TT + tt))*64;
        const uint32_t* sh = g_SH + b*8192;
        const uint32_t* sl = g_SL + b*8192;
        #pragma unroll
        for (int i = 0; i < 32; i++){
            int idx = i*256 + tid;
            int r = idx >> 6, p = idx & 63;
            su[XH  + r*PW + p] = gh[idx];
            su[XL  + r*PW + p] = gl[idx];
            su[WHo + r*PW + p] = sh[idx];
            su[WLo + r*PW + p] = sl[idx];
        }
    }
    __syncthreads();
    float acc[64];
    // o = phiq @ S  -> sTf
    wgemm<true>(su, XH, XL, WHo, WLo, acc, wm, wn, lane);
    #pragma unroll
    for (int mt = 0; mt < 4; mt++){
        int r0 = wm*64 + mt*16 + rg;
        #pragma unroll
        for (int nt = 0; nt < 4; nt++){
            int c0 = wn*32 + nt*8 + 2*tg, bs = (mt*4 + nt)*4;
            sTf[r0*132 + c0]       = acc[bs];
            sTf[r0*132 + c0 + 1]   = acc[bs+1];
            sTf[(r0+8)*132 + c0]   = acc[bs+2];
            sTf[(r0+8)*132 + c0+1] = acc[bs+3];
        }
    }
    __syncthreads();
    // RMSNorm warp-per-row; write onorm bf16 hi/lo into XH/XL
    for (int r = wid; r < 128; r += 8){
        float ss = 0.f;
        #pragma unroll
        for (int j = 0; j < 4; j++){
            float v = sTf[r*132 + lane + j*32];
            ss = fmaf(v, v, ss);
        }
        #pragma unroll
        for (int off = 16; off; off >>= 1) ss += __shfl_xor_sync(0xffffffffu, ss, off);
        float sc = rsqrtf(ss*(1.0f/128.0f) + EPSV);
        float w0 = sTf[r*132 + 4*lane]     * sc * sf[SB + 4*lane];
        float w1 = sTf[r*132 + 4*lane + 1] * sc * sf[SB + 4*lane + 1];
        float w2 = sTf[r*132 + 4*lane + 2] * sc * sf[SB + 4*lane + 2];
        float w3 = sTf[r*132 + 4*lane + 3] * sc * sf[SB + 4*lane + 3];
        su[XH + r*PW + 2*lane]     = packbf(w0, w1);
        su[XH + r*PW + 2*lane + 1] = packbf(w2, w3);
        su[XL + r*PW + 2*lane]     = packbf(bflo(w0), bflo(w1));
        su[XL + r*PW + 2*lane + 1] = packbf(bflo(w2), bflo(w3));
    }
    stageW(su, 5, tid);
    __syncthreads();
    // z = onorm @ Wo^T
    wgemm<true>(su, XH, XL, WHo, WLo, acc, wm, wn, lane);
    // column max: per-thread over mt rows, shfl over row-groups
    #pragma unroll
    for (int nt = 0; nt < 4; nt++){
        float m0 = -3.402823466e+38f, m1 = -3.402823466e+38f;
        #pragma unroll
        for (int mt = 0; mt < 4; mt++){
            int bs = (mt*4 + nt)*4;
            m0 = fmaxf(m0, fmaxf(acc[bs],   acc[bs+2]));
            m1 = fmaxf(m1, fmaxf(acc[bs+1], acc[bs+3]));
        }
        #pragma unroll
        for (int off = 4; off <= 16; off <<= 1){
            m0 = fmaxf(m0, __shfl_xor_sync(0xffffffffu, m0, off));
            m1 = fmaxf(m1, __shfl_xor_sync(0xffffffffu, m1, off));
        }
        if (lane < 4){
            int c0 = wn*32 + nt*8 + 2*tg;
            sf[RED + wm*128 + c0]     = m0;
            sf[RED + wm*128 + c0 + 1] = m1;
        }
    }
    __syncthreads();
    if (tid < 128){
        float m = fmaxf(sf[RED + tid], sf[RED + 128 + tid]);
        unsigned int bits = __float_as_uint(m);
        bits = (bits & 0x80000000u) ? ~bits : (bits | 0x80000000u);
        atomicMax(&g_poolbits[b*DD + tid], bits);
    }
}

// ---------------- final ----------------
__global__ void k_final(const float* __restrict__ Wp, const float* __restrict__ bp,
                        float* __restrict__ out)
{
    __shared__ float sp[DD];
    int b = blockIdx.x, h = threadIdx.x;
    if (h < DD){
        unsigned int e = g_poolbits[b*DD + h];
        e = (e & 0x80000000u) ? (e & 0x7fffffffu) : ~e;
        sp[h] = __uint_as_float(e);
    }
    __syncthreads();
    float s = bp[h];
    #pragma unroll 8
    for (int d = 0; d < DD; d++) s = fmaf(sp[d], Wp[h*DD + d], s);
    out[b*HH + h] = s;
}

// ---------------- launch ----------------
extern "C" void kernel_launch(void* const* d_in, const int* in_sizes, int n_in,
                              void* d_out, int out_size)
{
    (void)in_sizes; (void)n_in; (void)out_size;
    const float* x    = (const float*)d_in[0];
    const float* Wq   = (const float*)d_in[1];
    const float* Wk   = (const float*)d_in[2];
    const float* Wv   = (const float*)d_in[3];
    const float* fq1  = (const float*)d_in[4];
    const float* bq1  = (const float*)d_in[5];
    const float* fq2  = (const float*)d_in[6];
    const float* bq2  = (const float*)d_in[7];
    const float* fk1  = (const float*)d_in[8];
    const float* bk1  = (const float*)d_in[9];
    const float* fk2  = (const float*)d_in[10];
    const float* bk2  = (const float*)d_in[11];
    const float* rmsw = (const float*)d_in[12];
    const float* Wo   = (const float*)d_in[13];
    const float* Wp   = (const float*)d_in[14];
    const float* bp   = (const float*)d_in[15];
    float* out = (float*)d_out;

    cudaFuncSetAttribute(k_pass1, cudaFuncAttributeMaxDynamicSharedMemorySize, SMEMB);
    cudaFuncSetAttribute(k_pass2, cudaFuncAttributeMaxDynamicSharedMemorySize, SMEMB);

    k_prep<<<6, 256>>>(Wq, Wk, Wv, fq1, fq2, fk1, fk2, Wo);
    k_init<<<1, 256>>>();
    k_pass1<<<dim3(NS, BB), 256, SMEMB>>>(x, bq1, bq2, bk1, bk2);
    k_reduceS<<<512, 256>>>();
    k_pass2<<<dim3(128, BB), 256, SMEMB>>>(rmsw);
    k_final<<<BB, HH>>>(Wp, bp, out);
}